// round 15
// baseline (speedup 1.0000x reference)
#include <cuda_runtime.h>
#include <cstdint>
#include <math.h>

#define OFFD 131

__device__ float g_qH[512*128*32];
__device__ float g_kH[512*128*32];
__device__ float g_qW[512*128*32];
__device__ float g_kW[512*128*32];
__device__ float g_vH[512*128*256];
__device__ float g_vW[512*128*256];
__device__ float g_p0[128*128*320];
__device__ float g_EH[512*128*128];
__device__ float g_EW[512*128*128];
__device__ float g_cO[512*128*256];
__device__ float g_rO[512*128*256];
__device__ float g_dX[129][2];
__device__ float g_dY[129][2];
__device__ float g_Wt[256*320];
__device__ float g_bias[320];

typedef unsigned long long ull;

__device__ __forceinline__ void ffma2(ull& d, ull a, ull b) {
    asm("fma.rn.f32x2 %0, %1, %2, %0;" : "+l"(d) : "l"(a), "l"(b));
}
__device__ __forceinline__ ull dup2(float x) {
    ull r; asm("mov.b64 %0, {%1, %1};" : "=l"(r) : "f"(x)); return r;
}
__device__ __forceinline__ float2 u2f(ull v) {
    float2 f; asm("mov.b64 {%0, %1}, %2;" : "=f"(f.x), "=f"(f.y) : "l"(v)); return f;
}
__device__ __forceinline__ void cpa16(unsigned dst, const float* src) {
    asm volatile("cp.async.ca.shared.global [%0], [%1], 16;" :: "r"(dst), "l"(src));
}
__device__ __forceinline__ void cpa_commit() {
    asm volatile("cp.async.commit_group;");
}
template<int N> __device__ __forceinline__ void cpa_wait() {
    asm volatile("cp.async.wait_group %0;" :: "n"(N));
}
__device__ __forceinline__ void mma_tf32(float* d, const uint32_t* a, const uint32_t* b) {
    asm volatile("mma.sync.aligned.m16n8k8.row.col.f32.tf32.tf32.f32 "
                 "{%0,%1,%2,%3}, {%4,%5,%6,%7}, {%8,%9}, {%0,%1,%2,%3};"
                 : "+f"(d[0]), "+f"(d[1]), "+f"(d[2]), "+f"(d[3])
                 : "r"(a[0]), "r"(a[1]), "r"(a[2]), "r"(a[3]), "r"(b[0]), "r"(b[1]));
}
__device__ __forceinline__ uint32_t hi_part(uint32_t u) { return u & 0xFFFFE000u; }
__device__ __forceinline__ uint32_t lo_part(uint32_t u) {
    return __float_as_uint(__uint_as_float(u) - __uint_as_float(u & 0xFFFFE000u));
}

// ---- offset pooling + regloss ----
__global__ void kern_prep(const float* __restrict__ off, float* __restrict__ out, int regIdx)
{
    const int t = threadIdx.x;
    const float inv9 = 1.0f / 9.0f;
    for (int idx = t; idx < 258; idx += 512) {
        int r = idx % 129, ch = idx / 129;
        const float* o = off + ch * OFFD * OFFD;
        float s = 0.f;
        #pragma unroll
        for (int i = 0; i < 3; i++)
            #pragma unroll
            for (int j = 0; j < 3; j++) s += o[(r + i) * OFFD + 64 + j];
        g_dX[r][ch] = s * inv9;
    }
    for (int idx = t; idx < 258; idx += 512) {
        int c = idx % 129, ch = idx / 129;
        const float* o = off + ch * OFFD * OFFD;
        float s = 0.f;
        #pragma unroll
        for (int i = 0; i < 3; i++)
            #pragma unroll
            for (int j = 0; j < 3; j++) s += o[(64 + i) * OFFD + c + j];
        g_dY[c][ch] = s * inv9;
    }
    float s1 = 0.f, s2 = 0.f;
    for (int i = t; i < OFFD * OFFD; i += 512) {
        float d = off[i] - off[OFFD * OFFD + i];
        s1 += d * d;
    }
    for (int i = t; i < 2 * 130 * OFFD; i += 512) {
        int ch = i / (130 * OFFD);
        int rem = i - ch * 130 * OFFD;
        int r = rem / OFFD, c = rem - r * OFFD;
        float d = off[ch * OFFD * OFFD + r * OFFD + c] - off[ch * OFFD * OFFD + (r + 1) * OFFD + c];
        s2 += d * d;
    }
    __shared__ float sh1[512], sh2[512];
    sh1[t] = s1; sh2[t] = s2;
    __syncthreads();
    for (int s = 256; s > 0; s >>= 1) {
        if (t < s) { sh1[t] += sh1[t + s]; sh2[t] += sh2[t + s]; }
        __syncthreads();
    }
    if (t == 0)
        out[regIdx] = sh1[0] / (float)(OFFD * OFFD) + sh2[0] / (float)(2 * 130 * OFFD);
}

// ---- weight transpose ----
__global__ void kern_wt(const float* __restrict__ Wq, const float* __restrict__ bq,
                        const float* __restrict__ Wk, const float* __restrict__ bk,
                        const float* __restrict__ Wv, const float* __restrict__ bv)
{
    const int o = blockIdx.x;
    const int c = threadIdx.x;
    const float* row = (o < 32) ? (Wq + (size_t)o * 256)
                      : (o < 64) ? (Wk + (size_t)(o - 32) * 256)
                                 : (Wv + (size_t)(o - 64) * 256);
    g_Wt[(size_t)c * 320 + o] = row[c];
    if (c == 0)
        g_bias[o] = (o < 32) ? bq[o] : (o < 64) ? bk[o - 32] : bv[o - 64];
}

// smem: As[2][32][136] (34816 B) + Ws[2][32][72] (18432 B) = 53248 B
#define PSM_TOTAL 53248

// ---- Q/K projection via split-tf32 mma (softmax-safe): grid (h=128, 1, b=4), block 256 ----
// A tile stored k-major: As[c][w], loaded directly from x (contiguous rows).
__global__ __launch_bounds__(256) void kern_projqk_mma(const float* __restrict__ x)
{
    extern __shared__ __align__(16) float psm[];
    float* As = psm;             // [2][32][136]
    float* Ws = psm + 8704;      // [2][32][72]
    float (*Ot)[68] = (float (*)[68])psm;

    const int h = blockIdx.x, b = blockIdx.z;
    const int t = threadIdx.x;
    const int w = t >> 5, lane = t & 31;
    const int g = lane >> 2, tig = lane & 3;
    const int mbase = (w >> 1) * 32, nbase = (w & 1) * 32;
    const float* xb = x + (size_t)b * 256 * 16384 + (size_t)h * 128;  // + c*16384 + w
    const unsigned as_u = (unsigned)__cvta_generic_to_shared(As);
    const unsigned ws_u = (unsigned)__cvta_generic_to_shared(Ws);

    float acc[2][4][4];
    #pragma unroll
    for (int mt = 0; mt < 2; mt++)
        #pragma unroll
        for (int nt = 0; nt < 4; nt++)
            #pragma unroll
            for (int i = 0; i < 4; i++) acc[mt][nt][i] = 0.f;

    {
        #pragma unroll
        for (int r = 0; r < 4; r++) {
            int idx = t + r * 256;
            int c = idx >> 5, ws4 = (idx & 31) << 2;
            cpa16(as_u + (unsigned)((c * 136 + ws4) * 4), xb + (size_t)c * 16384 + ws4);
        }
        #pragma unroll
        for (int r = 0; r < 2; r++) {
            int idx = t + r * 256;
            int k = idx >> 4, o4 = (idx & 15) << 2;
            cpa16(ws_u + (unsigned)((k * 72 + o4) * 4), g_Wt + (size_t)k * 320 + o4);
        }
        cpa_commit();
    }

    for (int kc = 0; kc < 8; kc++) {
        const int buf = kc & 1;
        cpa_wait<0>();
        __syncthreads();
        if (kc < 7) {
            const int nb = buf ^ 1, kn = (kc + 1) * 32;
            #pragma unroll
            for (int r = 0; r < 4; r++) {
                int idx = t + r * 256;
                int c = idx >> 5, ws4 = (idx & 31) << 2;
                cpa16(as_u + (unsigned)((nb * 4352 + c * 136 + ws4) * 4),
                      xb + (size_t)(kn + c) * 16384 + ws4);
            }
            #pragma unroll
            for (int r = 0; r < 2; r++) {
                int idx = t + r * 256;
                int k = idx >> 4, o4 = (idx & 15) << 2;
                cpa16(ws_u + (unsigned)((nb * 2304 + k * 72 + o4) * 4),
                      g_Wt + (size_t)(kn + k) * 320 + o4);
            }
            cpa_commit();
        }
        const float* Ab = As + buf * 4352;
        const float* Wb = Ws + buf * 2304;
        #pragma unroll
        for (int hs = 0; hs < 4; hs++) {
            const int kb = hs * 8;
            uint32_t afh[2][4], afl[2][4];
            #pragma unroll
            for (int mt = 0; mt < 2; mt++) {
                const float* ar = Ab + (kb + tig) * 136 + mbase + mt * 16 + g;
                uint32_t a0 = __float_as_uint(ar[0]);
                uint32_t a1 = __float_as_uint(ar[8]);
                uint32_t a2 = __float_as_uint(ar[4 * 136]);
                uint32_t a3 = __float_as_uint(ar[4 * 136 + 8]);
                afh[mt][0] = hi_part(a0); afl[mt][0] = lo_part(a0);
                afh[mt][1] = hi_part(a1); afl[mt][1] = lo_part(a1);
                afh[mt][2] = hi_part(a2); afl[mt][2] = lo_part(a2);
                afh[mt][3] = hi_part(a3); afl[mt][3] = lo_part(a3);
            }
            #pragma unroll
            for (int nt = 0; nt < 4; nt++) {
                const float* br = Wb + (kb + tig) * 72 + nbase + nt * 8 + g;
                uint32_t b0 = __float_as_uint(br[0]);
                uint32_t b1 = __float_as_uint(br[4 * 72]);
                uint32_t bfh[2] = {hi_part(b0), hi_part(b1)};
                uint32_t bfl[2] = {lo_part(b0), lo_part(b1)};
                #pragma unroll
                for (int mt = 0; mt < 2; mt++) {
                    mma_tf32(acc[mt][nt], afh[mt], bfh);
                    mma_tf32(acc[mt][nt], afh[mt], bfl);
                    mma_tf32(acc[mt][nt], afl[mt], bfh);
                }
            }
        }
    }
    __syncthreads();

    #pragma unroll
    for (int mt = 0; mt < 2; mt++)
        #pragma unroll
        for (int nt = 0; nt < 4; nt++) {
            int row = mbase + mt * 16 + g;
            int col = nbase + nt * 8 + 2 * tig;
            float b0 = g_bias[col], b1 = g_bias[col + 1];
            Ot[row][col]     = acc[mt][nt][0] + b0;
            Ot[row][col + 1] = acc[mt][nt][1] + b1;
            Ot[row + 8][col]     = acc[mt][nt][2] + b0;
            Ot[row + 8][col + 1] = acc[mt][nt][3] + b1;
        }
    __syncthreads();

    {
        int ww = t >> 1, half = t & 1;
        const float* src = &Ot[ww][half * 32];
        if (b > 0) {
            float* dst = half ? (g_kH + (((size_t)(b * 128 + ww)) * 128 + h) * 32)
                              : (g_qH + (((size_t)(b * 128 + ww)) * 128 + h) * 32);
            #pragma unroll
            for (int i = 0; i < 8; i++) ((float4*)dst)[i] = ((const float4*)src)[i];
            float* dq = g_qW + ((size_t)(b * 128 + h)) * 4096;
            float* dk = g_kW + ((size_t)(b * 128 + h)) * 4096;
            #pragma unroll
            for (int r = 0; r < 4; r++) {
                int e = (t + r * 256) << 2;
                int wI = e >> 5, cI = e & 31;
                *(float4*)(dq + e) = *(const float4*)&Ot[wI][cI];
                *(float4*)(dk + e) = *(const float4*)&Ot[wI][32 + cI];
            }
        } else {
            float* dst = g_p0 + ((size_t)(h * 128 + ww)) * 320 + half * 32;
            #pragma unroll
            for (int i = 0; i < 8; i++) ((float4*)dst)[i] = ((const float4*)src)[i];
        }
    }
}

// ---- V projection via mma.sync tf32: grid (h=128, ot=4, b=4), block 256 ----
__global__ __launch_bounds__(256) void kern_projv(const float* __restrict__ x)
{
    extern __shared__ __align__(16) float psm[];
    float* As = psm;             // [2][32][136]
    float* Ws = psm + 8704;      // [2][32][72]
    float (*Ot)[68] = (float (*)[68])psm;

    const int h = blockIdx.x, ot = blockIdx.y, b = blockIdx.z;
    const int t = threadIdx.x;
    const int w = t >> 5, lane = t & 31;
    const int g = lane >> 2, tig = lane & 3;
    const int mbase = (w >> 1) * 32, nbase = (w & 1) * 32;
    const int oc = 64 + ot * 64;
    const float* xb = x + (size_t)b * 256 * 16384 + (size_t)h * 128;
    const unsigned as_u = (unsigned)__cvta_generic_to_shared(As);
    const unsigned ws_u = (unsigned)__cvta_generic_to_shared(Ws);

    float acc[2][4][4];
    #pragma unroll
    for (int mt = 0; mt < 2; mt++)
        #pragma unroll
        for (int nt = 0; nt < 4; nt++)
            #pragma unroll
            for (int i = 0; i < 4; i++) acc[mt][nt][i] = 0.f;

    {
        #pragma unroll
        for (int r = 0; r < 4; r++) {
            int idx = t + r * 256;
            int c = idx >> 5, ws4 = (idx & 31) << 2;
            cpa16(as_u + (unsigned)((c * 136 + ws4) * 4), xb + (size_t)c * 16384 + ws4);
        }
        #pragma unroll
        for (int r = 0; r < 2; r++) {
            int idx = t + r * 256;
            int k = idx >> 4, o4 = (idx & 15) << 2;
            cpa16(ws_u + (unsigned)((k * 72 + o4) * 4), g_Wt + (size_t)k * 320 + oc + o4);
        }
        cpa_commit();
    }

    for (int kc = 0; kc < 8; kc++) {
        const int buf = kc & 1;
        cpa_wait<0>();
        __syncthreads();
        if (kc < 7) {
            const int nb = buf ^ 1, kn = (kc + 1) * 32;
            #pragma unroll
            for (int r = 0; r < 4; r++) {
                int idx = t + r * 256;
                int c = idx >> 5, ws4 = (idx & 31) << 2;
                cpa16(as_u + (unsigned)((nb * 4352 + c * 136 + ws4) * 4),
                      xb + (size_t)(kn + c) * 16384 + ws4);
            }
            #pragma unroll
            for (int r = 0; r < 2; r++) {
                int idx = t + r * 256;
                int k = idx >> 4, o4 = (idx & 15) << 2;
                cpa16(ws_u + (unsigned)((nb * 2304 + k * 72 + o4) * 4),
                      g_Wt + (size_t)(kn + k) * 320 + oc + o4);
            }
            cpa_commit();
        }
        const float* Ab = As + buf * 4352;
        const float* Wb = Ws + buf * 2304;
        #pragma unroll
        for (int hs = 0; hs < 4; hs++) {
            const int kb = hs * 8;
            uint32_t af[2][4];
            #pragma unroll
            for (int mt = 0; mt < 2; mt++) {
                const float* ar = Ab + (kb + tig) * 136 + mbase + mt * 16 + g;
                af[mt][0] = __float_as_uint(ar[0]);
                af[mt][1] = __float_as_uint(ar[8]);
                af[mt][2] = __float_as_uint(ar[4 * 136]);
                af[mt][3] = __float_as_uint(ar[4 * 136 + 8]);
            }
            #pragma unroll
            for (int nt = 0; nt < 4; nt++) {
                const float* br = Wb + (kb + tig) * 72 + nbase + nt * 8 + g;
                uint32_t bf[2];
                bf[0] = __float_as_uint(br[0]);
                bf[1] = __float_as_uint(br[4 * 72]);
                mma_tf32(acc[0][nt], af[0], bf);
                mma_tf32(acc[1][nt], af[1], bf);
            }
        }
    }
    __syncthreads();

    #pragma unroll
    for (int mt = 0; mt < 2; mt++)
        #pragma unroll
        for (int nt = 0; nt < 4; nt++) {
            int row = mbase + mt * 16 + g;
            int col = nbase + nt * 8 + 2 * tig;
            float b0 = g_bias[oc + col], b1 = g_bias[oc + col + 1];
            Ot[row][col]     = acc[mt][nt][0] + b0;
            Ot[row][col + 1] = acc[mt][nt][1] + b1;
            Ot[row + 8][col]     = acc[mt][nt][2] + b0;
            Ot[row + 8][col + 1] = acc[mt][nt][3] + b1;
        }
    __syncthreads();

    {
        const int c0v = ot * 64;
        int ww = t >> 1, half = t & 1;
        const float* src = &Ot[ww][half * 32];
        if (b > 0) {
            float* dst = g_vH + (((size_t)(b * 128 + ww)) * 128 + h) * 256 + c0v + half * 32;
            #pragma unroll
            for (int i = 0; i < 8; i++) ((float4*)dst)[i] = ((const float4*)src)[i];
            float* dw = g_vW + ((size_t)(b * 128 + h)) * 32768 + c0v;
            #pragma unroll
            for (int r = 0; r < 8; r++) {
                int e = (t + r * 256) << 2;
                int wI = e >> 6, cI = e & 63;
                *(float4*)(dw + (size_t)wI * 256 + cI) = *(const float4*)&Ot[wI][cI];
            }
        } else {
            float* dst = g_p0 + ((size_t)(h * 128 + ww)) * 320 + 64 + c0v + half * 32;
            #pragma unroll
            for (int i = 0; i < 8; i++) ((float4*)dst)[i] = ((const float4*)src)[i];
        }
    }
}

// ---- deformable bilinear sampling: grid (16384, 2), block 320 ----
__global__ void kern_sample()
{
    const int pt = blockIdx.x, br = blockIdx.y;
    const int k = pt >> 7, pos = pt & 127;
    float px, py;
    if (br == 0) {
        int r = pos + 1;
        px = (-1.0f + k * 0.015625f) + g_dX[r][0];
        py = (-1.0f + r * 0.015625f) + g_dX[r][1];
    } else {
        int ci = pos + 1;
        px = (-1.0f + ci * 0.015625f) + g_dY[ci][0];
        py = (-1.0f + k * 0.015625f) + g_dY[ci][1];
    }
    float fx = (px + 1.0f) * 0.5f * 127.0f;
    float fy = (py + 1.0f) * 0.5f * 127.0f;
    float x0f = floorf(fx), y0f = floorf(fy);
    float wx = fx - x0f, wy = fy - y0f;
    int x0 = (int)x0f, y0 = (int)y0f;
    bool vx0 = (x0 >= 0) && (x0 < 128);
    bool vx1 = (x0 + 1 >= 0) && (x0 + 1 < 128);
    bool vy0 = (y0 >= 0) && (y0 < 128);
    bool vy1 = (y0 + 1 >= 0) && (y0 + 1 < 128);

    const int c = threadIdx.x;
    float acc = 0.f;
    if (vx0 && vy0) acc += g_p0[((size_t)(y0 * 128 + x0)) * 320 + c] * ((1.f - wx) * (1.f - wy));
    if (vx1 && vy0) acc += g_p0[((size_t)(y0 * 128 + x0 + 1)) * 320 + c] * (wx * (1.f - wy));
    if (vx0 && vy1) acc += g_p0[((size_t)((y0 + 1) * 128 + x0)) * 320 + c] * ((1.f - wx) * wy);
    if (vx1 && vy1) acc += g_p0[((size_t)((y0 + 1) * 128 + x0 + 1)) * 320 + c] * (wx * wy);

    size_t lp = (size_t)k * 128 + pos;
    if (br == 0) {
        if (c < 32)      g_qH[lp * 32 + c] = acc;
        else if (c < 64) g_kH[lp * 32 + (c - 32)] = acc;
        else             g_vH[lp * 256 + (c - 64)] = acc;
    } else {
        if (c < 32)      g_qW[lp * 32 + c] = acc;
        else if (c < 64) g_kW[lp * 32 + (c - 32)] = acc;
        else             g_vW[lp * 256 + (c - 64)] = acc;
    }
}

// ---- per-line energy GEMM E = Q @ K^T: grid (512, 2), block 256 ----
__global__ __launch_bounds__(256) void kern_energy()
{
    __shared__ __align__(16) float Qt[32][132];
    __shared__ __align__(16) float Kt[32][132];
    const int l = blockIdx.x, br = blockIdx.y;
    const float* Q = (br ? g_qW : g_qH) + (size_t)l * 4096;
    const float* K = (br ? g_kW : g_kH) + (size_t)l * 4096;
    float* E = (br ? g_EW : g_EH) + (size_t)l * 16384;
    const int t = threadIdx.x;

    #pragma unroll
    for (int r = 0; r < 4; r++) {
        int lin = t + r * 256;
        int p = lin >> 3, c4 = (lin & 7) << 2;
        float4 q = *(const float4*)(Q + (size_t)p * 32 + c4);
        Qt[c4][p] = q.x; Qt[c4 + 1][p] = q.y; Qt[c4 + 2][p] = q.z; Qt[c4 + 3][p] = q.w;
        float4 kk = *(const float4*)(K + (size_t)p * 32 + c4);
        Kt[c4][p] = kk.x; Kt[c4 + 1][p] = kk.y; Kt[c4 + 2][p] = kk.z; Kt[c4 + 3][p] = kk.w;
    }
    __syncthreads();

    const int tj = t & 15, ti = t >> 4;
    const int i0 = ti * 8, j0 = tj * 8;
    ull acc2[8][4];
    #pragma unroll
    for (int u = 0; u < 8; u++)
        #pragma unroll
        for (int v = 0; v < 4; v++) acc2[u][v] = 0ULL;

    #pragma unroll
    for (int c = 0; c < 32; c++) {
        float4 qa = *(const float4*)&Qt[c][i0];
        float4 qb = *(const float4*)&Qt[c][i0 + 4];
        ull ad[8] = {dup2(qa.x), dup2(qa.y), dup2(qa.z), dup2(qa.w),
                     dup2(qb.x), dup2(qb.y), dup2(qb.z), dup2(qb.w)};
        const ull* kp = (const ull*)&Kt[c][j0];
        ull b0 = kp[0], b1 = kp[1], b2 = kp[2], b3 = kp[3];
        #pragma unroll
        for (int u = 0; u < 8; u++) {
            ffma2(acc2[u][0], ad[u], b0);
            ffma2(acc2[u][1], ad[u], b1);
            ffma2(acc2[u][2], ad[u], b2);
            ffma2(acc2[u][3], ad[u], b3);
        }
    }
    #pragma unroll
    for (int u = 0; u < 8; u++) {
        float2 p0 = u2f(acc2[u][0]), p1 = u2f(acc2[u][1]);
        float2 p2 = u2f(acc2[u][2]), p3 = u2f(acc2[u][3]);
        *(float4*)(E + (size_t)(i0 + u) * 128 + j0)     = make_float4(p0.x, p0.y, p1.x, p1.y);
        *(float4*)(E + (size_t)(i0 + u) * 128 + j0 + 4) = make_float4(p2.x, p2.y, p3.x, p3.y);
    }
}

// ---- joint softmax ----
__global__ void kern_softmax()
{
    int gw = (blockIdx.x * blockDim.x + threadIdx.x) >> 5;
    int lane = threadIdx.x & 31;
    if (gw >= 65536) return;
    int b = gw >> 14;
    int rem = gw & 16383;
    int h = rem >> 7, w = rem & 127;
    float* r1 = g_EH + (((size_t)(b * 128 + w)) * 128 + h) * 128;
    float* r2 = g_EW + (((size_t)(b * 128 + h)) * 128 + w) * 128;
    float4 a = *(float4*)(r1 + lane * 4);
    float4 c = *(float4*)(r2 + lane * 4);
    float e1[4] = {a.x, a.y, a.z, a.w};
    float e2[4] = {c.x, c.y, c.z, c.w};
    float m = -INFINITY;
    #pragma unroll
    for (int u = 0; u < 4; u++) {
        if (lane * 4 + u != h) m = fmaxf(m, e1[u]);
        m = fmaxf(m, e2[u]);
    }
    #pragma unroll
    for (int s = 16; s > 0; s >>= 1) m = fmaxf(m, __shfl_xor_sync(0xffffffffu, m, s));
    float sum = 0.f;
    #pragma unroll
    for (int u = 0; u < 4; u++) {
        e1[u] = (lane * 4 + u == h) ? 0.f : __expf(e1[u] - m);
        sum += e1[u];
        e2[u] = __expf(e2[u] - m);
        sum += e2[u];
    }
    #pragma unroll
    for (int s = 16; s > 0; s >>= 1) sum += __shfl_xor_sync(0xffffffffu, sum, s);
    float inv = 1.0f / sum;
    *(float4*)(r1 + lane * 4) = make_float4(e1[0] * inv, e1[1] * inv, e1[2] * inv, e1[3] * inv);
    *(float4*)(r2 + lane * 4) = make_float4(e2[0] * inv, e2[1] * inv, e2[2] * inv, e2[3] * inv);
}

// ---- per-line output GEMM via mma.sync tf32 ----
// smem: As[2][128][36] (36864 B) + Vs[2][32][136] (34816 B) = 71680 B
#define OSM_TOTAL 71680

__global__ __launch_bounds__(256) void kern_out_mma()
{
    extern __shared__ __align__(16) float osm[];
    float* As = osm;             // [2][128][36]
    float* Vs = osm + 9216;      // [2][32][136]
    const int l = blockIdx.x, chf = blockIdx.y, br = blockIdx.z;
    const float* A = (br ? g_EW : g_EH) + (size_t)l * 16384;
    const float* V = (br ? g_vW : g_vH) + (size_t)l * 32768 + chf * 128;
    float* O = (br ? g_rO : g_cO) + (size_t)l * 32768 + chf * 128;
    const int t = threadIdx.x;
    const int w = t >> 5, lane = t & 31;
    const int g = lane >> 2, tig = lane & 3;
    const int kbase = (w >> 1) * 32, cbase = (w & 1) * 64;
    const unsigned as_u = (unsigned)__cvta_generic_to_shared(As);
    const unsigned vs_u = (unsigned)__cvta_generic_to_shared(Vs);

    float acc[2][8][4];
    #pragma unroll
    for (int mt = 0; mt < 2; mt++)
        #pragma unroll
        for (int nt = 0; nt < 8; nt++)
            #pragma unroll
            for (int i = 0; i < 4; i++) acc[mt][nt][i] = 0.f;

    {
        #pragma unroll
        for (int r = 0; r < 4; r++) {
            int idx = t + r * 256;
            int k = idx >> 3, seg = idx & 7;
            cpa16(as_u + (unsigned)((k * 36 + seg * 4) * 4), A + (size_t)k * 128 + seg * 4);
        }
        #pragma unroll
        for (int r = 0; r < 4; r++) {
            int idx = t + r * 256;
            int hh = idx >> 5, seg = idx & 31;
            cpa16(vs_u + (unsigned)((hh * 136 + seg * 4) * 4), V + (size_t)hh * 256 + seg * 4);
        }
        cpa_commit();
    }

    for (int hc = 0; hc < 4; hc++) {
        const int buf = hc & 1;
        cpa_wait<0>();
        __syncthreads();
        if (hc < 3) {
            const int nb = buf ^ 1, hn = (hc + 1) * 32;
            #pragma unroll
            for (int r = 0; r < 4; r++) {
                int idx = t + r * 256;
                int k = idx >> 3, seg = idx & 7;
                cpa16(as_u + (unsigned)((nb * 4608 + k * 36 + seg * 4) * 4),
                      A + (size_t)k * 128 + hn + seg * 4);
            }
            #pragma unroll
            for (int r = 0; r < 4; r++) {
                int idx = t + r * 256;
                int hh = idx >> 5, seg = idx & 31;
                cpa16(vs_u + (unsigned)((nb * 4352 + hh * 136 + seg * 4) * 4),
                      V + (size_t)(hn + hh) * 256 + seg * 4);
            }
            cpa_commit();
        }
        const float* Ab = As + buf * 4608;
        const float* Vb = Vs + buf * 4352;
        #pragma unroll
        for (int hs = 0; hs < 4; hs++) {
            const int hb = hs * 8;
            uint32_t af[2][4];
            #pragma unroll
            for (int mt = 0; mt < 2; mt++) {
                const float* ar = Ab + (kbase + mt * 16 + g) * 36 + hb + tig;
                af[mt][0] = __float_as_uint(ar[0]);
                af[mt][1] = __float_as_uint(ar[8 * 36]);
                af[mt][2] = __float_as_uint(ar[4]);
                af[mt][3] = __float_as_uint(ar[8 * 36 + 4]);
            }
            #pragma unroll
            for (int nt = 0; nt < 8; nt++) {
                const float* vr = Vb + (hb + tig) * 136 + cbase + nt * 8 + g;
                uint32_t bf[2];
                bf[0] = __float_as_uint(vr[0]);
                bf[1] = __float_as_uint(vr[4 * 136]);
                mma_tf32(acc[0][nt], af[0], bf);
                mma_tf32(acc[1][nt], af[1], bf);
            }
        }
    }

    #pragma unroll
    for (int mt = 0; mt < 2; mt++)
        #pragma unroll
        for (int nt = 0; nt < 8; nt++) {
            int row = kbase + mt * 16 + g;
            int col = cbase + nt * 8 + 2 * tig;
            *(float2*)(O + (size_t)row * 256 + col)       = make_float2(acc[mt][nt][0], acc[mt][nt][1]);
            *(float2*)(O + (size_t)(row + 8) * 256 + col) = make_float2(acc[mt][nt][2], acc[mt][nt][3]);
        }
}

// ---- combine ----
__global__ void kern_combine(const float* __restrict__ x, const float* __restrict__ gamma,
                             float* __restrict__ out)
{
    __shared__ __align__(16) float s[32][132];
    const int h = blockIdx.x, ct = blockIdx.y, b = blockIdx.z;
    const int c0 = ct * 32, t = threadIdx.x;
    #pragma unroll
    for (int r = 0; r < 4; r++) {
        int lin = t + r * 256;
        int w = lin >> 3, c4 = (lin & 7) << 2;
        float4 a = *(const float4*)(g_cO + (((size_t)(b * 128 + w)) * 128 + h) * 256 + c0 + c4);
        float4 bb = *(const float4*)(g_rO + (((size_t)(b * 128 + h)) * 128 + w) * 256 + c0 + c4);
        s[c4][w] = a.x + bb.x; s[c4 + 1][w] = a.y + bb.y;
        s[c4 + 2][w] = a.z + bb.z; s[c4 + 3][w] = a.w + bb.w;
    }
    __syncthreads();
    float g = gamma[0];
    #pragma unroll
    for (int r = 0; r < 4; r++) {
        int lin = t + r * 256;
        int c = lin >> 5, w4 = (lin & 31) << 2;
        size_t oidx = (((size_t)b * 256 + c0 + c) * 128 + h) * 128 + w4;
        float4 xv = *(const float4*)(x + oidx);
        float4 o;
        o.x = g * s[c][w4] + xv.x;
        o.y = g * s[c][w4 + 1] + xv.y;
        o.z = g * s[c][w4 + 2] + xv.z;
        o.w = g * s[c][w4 + 3] + xv.w;
        *(float4*)(out + oidx) = o;
    }
}

extern "C" void kernel_launch(void* const* d_in, const int* in_sizes, int n_in,
                              void* d_out, int out_size)
{
    const float* x      = (const float*)d_in[0];
    const float* Wq     = (const float*)d_in[1];
    const float* bq     = (const float*)d_in[2];
    const float* Wk     = (const float*)d_in[3];
    const float* bk     = (const float*)d_in[4];
    const float* Wv     = (const float*)d_in[5];
    const float* bv     = (const float*)d_in[6];
    const float* gamma  = (const float*)d_in[7];
    const float* offs   = (const float*)d_in[8];
    float* out = (float*)d_out;

    cudaFuncSetAttribute(kern_out_mma, cudaFuncAttributeMaxDynamicSharedMemorySize, OSM_TOTAL);
    cudaFuncSetAttribute(kern_projv, cudaFuncAttributeMaxDynamicSharedMemorySize, PSM_TOTAL);
    cudaFuncSetAttribute(kern_projqk_mma, cudaFuncAttributeMaxDynamicSharedMemorySize, PSM_TOTAL);
    cudaFuncSetAttribute(kern_out_mma, cudaFuncAttributePreferredSharedMemoryCarveout, 100);
    cudaFuncSetAttribute(kern_projv, cudaFuncAttributePreferredSharedMemoryCarveout, 100);
    cudaFuncSetAttribute(kern_projqk_mma, cudaFuncAttributePreferredSharedMemoryCarveout, 100);

    kern_prep<<<1, 512>>>(offs, out, out_size - 1);
    kern_wt<<<320, 256>>>(Wq, bq, Wk, bk, Wv, bv);
    kern_projqk_mma<<<dim3(128, 1, 4), 256, PSM_TOTAL>>>(x);
    kern_projv<<<dim3(128, 4, 4), 256, PSM_TOTAL>>>(x);
    kern_sample<<<dim3(16384, 2), 320>>>();
    kern_energy<<<dim3(512, 2), 256>>>();
    kern_softmax<<<8192, 256>>>();
    kern_out_mma<<<dim3(512, 2, 2), 256, OSM_TOTAL>>>();
    kern_combine<<<dim3(128, 8, 4), 256>>>(x, gamma, out);
}